// round 1
// baseline (speedup 1.0000x reference)
#include <cuda_runtime.h>
#include <math.h>

#define NSEQ 250000
#define LIN 40
#define CIN 20
#define KW 4
#define DIM 32
#define L1OUT 37   /* 40-4+1 */
#define L2OUT 34   /* 37-4+1 */
#define NBAGS 100
#define SEQ_PER_BLOCK 4
#define H1STRIDE 33  /* padded to kill 32-way bank conflicts */

// scratch (allocation-free rule: __device__ globals)
__device__ float g_embed[NSEQ * DIM];   // 32 MB
__device__ float g_scores[NSEQ];        // 1 MB

__device__ __forceinline__ float selu_f(float x) {
    const float a = 1.6732632423543772f, s = 1.0507009873554805f;
    return x > 0.f ? s * x : s * a * expm1f(x);
}
// monotonic float<->uint mapping so unsigned max == float max (deterministic)
__device__ __forceinline__ unsigned fmono(float x) {
    unsigned u = __float_as_uint(x);
    return (u & 0x80000000u) ? ~u : (u | 0x80000000u);
}
__device__ __forceinline__ float fmono_inv(unsigned u) {
    return (u & 0x80000000u) ? __uint_as_float(u ^ 0x80000000u)
                             : __uint_as_float(~u);
}

// ---------------------------------------------------------------------------
// Kernel A: per-sequence CNN + max-pool + attention MLP
// 128 threads = 4 warps, 4 sequences per block (1 seq per warp for the MLP).
// ---------------------------------------------------------------------------
__global__ __launch_bounds__(128) void seq_kernel(
    const float* __restrict__ x,
    const float* __restrict__ w1, const float* __restrict__ b1,
    const float* __restrict__ w2, const float* __restrict__ b2,
    const float* __restrict__ aw1, const float* __restrict__ ab1,
    const float* __restrict__ aw2, const float* __restrict__ ab2,
    const float* __restrict__ aw3, const float* __restrict__ ab3)
{
    __shared__ float w1s[KW * CIN * DIM];              // 2560 floats
    __shared__ float w2s[KW * DIM * DIM];              // 4096 floats
    __shared__ float b1s[DIM], b2s[DIM];
    __shared__ float h1s[SEQ_PER_BLOCK * L1OUT * H1STRIDE];  // 4884 floats
    __shared__ unsigned smax[SEQ_PER_BLOCK * DIM];           // 128

    const int tid = threadIdx.x;
    for (int i = tid; i < KW * CIN * DIM; i += 128) w1s[i] = w1[i];
    for (int i = tid; i < KW * DIM * DIM; i += 128) w2s[i] = w2[i];
    if (tid < DIM) { b1s[tid] = b1[tid]; b2s[tid] = b2[tid]; }
    if (tid < SEQ_PER_BLOCK * DIM) smax[tid] = 0u;  // 0 < mono(any float)
    __syncthreads();

    const long base_seq = (long)blockIdx.x * SEQ_PER_BLOCK;

    // ---- conv1 + SELU -> h1s (position per lane; leftovers in warp 0) ----
    for (int pass = 0; pass < 2; ++pass) {
        if (pass == 1 && tid >= SEQ_PER_BLOCK * L1OUT - 128) break;  // tid<20
        const int idx = pass == 0 ? tid : 128 + tid;
        const int seq = idx / L1OUT, t = idx % L1OUT;
        const float4* xv4 = reinterpret_cast<const float4*>(
            x + (base_seq + seq) * (long)(LIN * CIN) + t * CIN);
        float acc[DIM];
        #pragma unroll
        for (int d = 0; d < DIM; ++d) acc[d] = b1s[d];
        #pragma unroll 2
        for (int q = 0; q < (KW * CIN) / 4; ++q) {   // 20 x float4 = 80 taps
            const float4 xv = xv4[q];
            const float* wr = &w1s[q * 4 * DIM];
            #pragma unroll
            for (int d = 0; d < DIM; ++d) acc[d] = fmaf(xv.x, wr[d], acc[d]);
            #pragma unroll
            for (int d = 0; d < DIM; ++d) acc[d] = fmaf(xv.y, wr[DIM + d], acc[d]);
            #pragma unroll
            for (int d = 0; d < DIM; ++d) acc[d] = fmaf(xv.z, wr[2 * DIM + d], acc[d]);
            #pragma unroll
            for (int d = 0; d < DIM; ++d) acc[d] = fmaf(xv.w, wr[3 * DIM + d], acc[d]);
        }
        float* hout = &h1s[seq * (L1OUT * H1STRIDE) + t * H1STRIDE];
        #pragma unroll
        for (int d = 0; d < DIM; ++d) hout[d] = selu_f(acc[d]);
    }
    __syncthreads();

    // ---- conv2 + SELU + running max (monotonic atomicMax in smem) ----
    for (int pass = 0; pass < 2; ++pass) {
        if (pass == 1 && tid >= SEQ_PER_BLOCK * L2OUT - 128) break;  // tid<8
        const int idx = pass == 0 ? tid : 128 + tid;
        const int seq = idx / L2OUT, p = idx % L2OUT;
        float acc[DIM];
        #pragma unroll
        for (int d = 0; d < DIM; ++d) acc[d] = b2s[d];
        const float* hrow = &h1s[seq * (L1OUT * H1STRIDE) + p * H1STRIDE];
        #pragma unroll
        for (int k = 0; k < KW; ++k) {
            const float* hk = hrow + k * H1STRIDE;
            const float* wk = &w2s[k * DIM * DIM];
            #pragma unroll 4
            for (int c = 0; c < DIM; ++c) {
                const float hv = hk[c];
                const float* wr = &wk[c * DIM];
                #pragma unroll
                for (int d = 0; d < DIM; ++d) acc[d] = fmaf(hv, wr[d], acc[d]);
            }
        }
        unsigned* sm = &smax[seq * DIM];
        #pragma unroll
        for (int d = 0; d < DIM; ++d) atomicMax(&sm[d], fmono(selu_f(acc[d])));
    }
    __syncthreads();

    // decode mono-max -> float seq_embed (in place)
    float* es = reinterpret_cast<float*>(smax);
    if (tid < SEQ_PER_BLOCK * DIM) {
        const unsigned u = smax[tid];
        es[tid] = fmono_inv(u);
    }
    __syncthreads();

    // ---- attention MLP: warp w handles sequence w ----
    const int w = tid >> 5, j = tid & 31;
    const float* e = &es[w * DIM];

    float a1 = __ldg(&ab1[j]);
    #pragma unroll 8
    for (int i = 0; i < DIM; ++i)
        a1 = fmaf(e[i], __ldg(&aw1[i * DIM + j]), a1);
    a1 = selu_f(a1);

    float a2 = __ldg(&ab2[j]);
    #pragma unroll 8
    for (int i = 0; i < DIM; ++i)
        a2 = fmaf(__shfl_sync(0xffffffffu, a1, i), __ldg(&aw2[i * DIM + j]), a2);
    a2 = selu_f(a2);

    float sc = a2 * __ldg(&aw3[j]);
    #pragma unroll
    for (int o = 16; o > 0; o >>= 1) sc += __shfl_xor_sync(0xffffffffu, sc, o);

    const long n = base_seq + w;
    g_embed[n * DIM + j] = e[j];
    if (j == 0) g_scores[n] = sc + __ldg(&ab3[0]);
}

// ---------------------------------------------------------------------------
// Kernel B: per-bag segment softmax + pooling + output heads
// one block per bag, 256 threads, fixed-order reductions (deterministic)
// ---------------------------------------------------------------------------
__global__ __launch_bounds__(256) void bag_kernel(
    const int* __restrict__ nper,
    const float* __restrict__ oaw1, const float* __restrict__ oab1,
    const float* __restrict__ oaw2, const float* __restrict__ oab2,
    const float* __restrict__ obw1, const float* __restrict__ obb1,
    const float* __restrict__ obw2, const float* __restrict__ obb2,
    float* __restrict__ out)
{
    __shared__ float red[256];
    __shared__ float part[8][DIM];
    __shared__ float pooled[DIM];
    __shared__ float hA[DIM], hB[DIM];
    __shared__ int s_off, s_cnt;
    __shared__ float s_max, s_denom;

    const int tid = threadIdx.x, b = blockIdx.x;
    if (tid == 0) {
        int off = 0;
        for (int i = 0; i < b; ++i) off += nper[i];
        s_off = off; s_cnt = nper[b];
    }
    __syncthreads();
    const int off = s_off, cnt = s_cnt;

    // segment max
    float lm = -INFINITY;
    for (int i = tid; i < cnt; i += 256) lm = fmaxf(lm, g_scores[off + i]);
    red[tid] = lm; __syncthreads();
    for (int s = 128; s > 0; s >>= 1) {
        if (tid < s) red[tid] = fmaxf(red[tid], red[tid + s]);
        __syncthreads();
    }
    if (tid == 0) s_max = red[0];
    __syncthreads();
    const float mx = s_max;

    // segment sum of exp
    float ls = 0.f;
    for (int i = tid; i < cnt; i += 256) ls += expf(g_scores[off + i] - mx);
    red[tid] = ls; __syncthreads();
    for (int s = 128; s > 0; s >>= 1) {
        if (tid < s) red[tid] += red[tid + s];
        __syncthreads();
    }
    if (tid == 0) s_denom = red[0];
    __syncthreads();
    const float denom = s_denom;

    // weighted-sum pooling: 8 groups of 32 lanes, lane = channel
    const int g = tid >> 5, c = tid & 31;
    float acc = 0.f;
    for (int p = g; p < cnt; p += 8) {
        const float wgt = expf(g_scores[off + p] - mx);
        acc = fmaf(wgt, g_embed[(long)(off + p) * DIM + c], acc);
    }
    part[g][c] = acc;
    __syncthreads();
    if (tid < DIM) {
        float s = 0.f;
        #pragma unroll
        for (int gg = 0; gg < 8; ++gg) s += part[gg][tid];
        pooled[tid] = s / denom;
    }
    __syncthreads();

    // output heads: hidden layers (A: lanes 0..31, B: lanes 32..63)
    if (tid < DIM) {
        float v = __ldg(&oab1[tid]);
        #pragma unroll 8
        for (int i = 0; i < DIM; ++i) v = fmaf(pooled[i], __ldg(&oaw1[i * DIM + tid]), v);
        hA[tid] = selu_f(v);
    } else if (tid < 2 * DIM) {
        const int j = tid - DIM;
        float v = __ldg(&obb1[j]);
        #pragma unroll 8
        for (int i = 0; i < DIM; ++i) v = fmaf(pooled[i], __ldg(&obw1[i * DIM + j]), v);
        hB[j] = selu_f(v);
    }
    __syncthreads();

    // final layers + sigmoid; pa: (100,21) then pb: (100,40), row-major
    if (tid < 21) {
        float v = __ldg(&oab2[tid]);
        #pragma unroll 8
        for (int i = 0; i < DIM; ++i) v = fmaf(hA[i], __ldg(&oaw2[i * 21 + tid]), v);
        out[b * 21 + tid] = 1.f / (1.f + expf(-v));
    } else if (tid >= 64 && tid < 104) {
        const int k = tid - 64;
        float v = __ldg(&obb2[k]);
        #pragma unroll 8
        for (int i = 0; i < DIM; ++i) v = fmaf(hB[i], __ldg(&obw2[i * 40 + k]), v);
        out[NBAGS * 21 + b * 40 + k] = 1.f / (1.f + expf(-v));
    }
}

extern "C" void kernel_launch(void* const* d_in, const int* in_sizes, int n_in,
                              void* d_out, int out_size)
{
    (void)in_sizes; (void)n_in; (void)out_size;
    const float* x    = (const float*)d_in[0];
    const int*   nper = (const int*)  d_in[1];
    const float* w1   = (const float*)d_in[2];
    const float* b1   = (const float*)d_in[3];
    const float* w2   = (const float*)d_in[4];
    const float* b2   = (const float*)d_in[5];
    const float* aw1  = (const float*)d_in[6];
    const float* ab1  = (const float*)d_in[7];
    const float* aw2  = (const float*)d_in[8];
    const float* ab2  = (const float*)d_in[9];
    const float* aw3  = (const float*)d_in[10];
    const float* ab3  = (const float*)d_in[11];
    const float* oaw1 = (const float*)d_in[12];
    const float* oab1 = (const float*)d_in[13];
    const float* oaw2 = (const float*)d_in[14];
    const float* oab2 = (const float*)d_in[15];
    const float* obw1 = (const float*)d_in[16];
    const float* obb1 = (const float*)d_in[17];
    const float* obw2 = (const float*)d_in[18];
    const float* obb2 = (const float*)d_in[19];

    seq_kernel<<<NSEQ / SEQ_PER_BLOCK, 128>>>(
        x, w1, b1, w2, b2, aw1, ab1, aw2, ab2, aw3, ab3);
    bag_kernel<<<NBAGS, 256>>>(
        nper, oaw1, oab1, oaw2, oab2, obw1, obb1, obw2, obb2, (float*)d_out);
}

// round 2
// speedup vs baseline: 4.0843x; 4.0843x over previous
#include <cuda_runtime.h>
#include <math.h>

#define NSEQ 250000
#define LIN 40
#define CIN 20
#define KW 4
#define DIM 32
#define L1OUT 37   /* 40-4+1 */
#define L2OUT 34   /* 37-4+1 */
#define NBAGS 100
#define TSEQ 8                 /* sequences per block */
#define NBLK (NSEQ / TSEQ)     /* 31250 */
#define R1 (TSEQ * L1OUT)      /* 296 conv1 rows */
#define R2 (TSEQ * L2OUT)      /* 272 conv2 rows */
#define T1 ((R1 + 15) / 16)    /* 19 m-tiles (last partial) */
#define T2 (R2 / 16)           /* 17 m-tiles (exact) */
#define H1STRIDE 36            /* padded row stride: banks (4p+c)%32 distinct */
#define H1SEQ (L1OUT * H1STRIDE) /* 1332 */
#define NCHUNK 25

/* smem layout (floats) */
#define OFF_XS   0
#define OFF_H1   (OFF_XS + TSEQ * LIN * CIN)        /* 6400  */
#define OFF_BF1  (OFF_H1 + TSEQ * H1SEQ)            /* 17056 */
#define OFF_BF2  (OFF_BF1 + 10 * 4 * 32 * 2)        /* 19616 */
#define OFF_B1   (OFF_BF2 + 16 * 4 * 32 * 2)        /* 23712 */
#define OFF_B2   (OFF_B1 + 32)                      /* 23744 */
#define OFF_SMAX (OFF_B2 + 32)                      /* 23776 */
#define SMEM_FLOATS (OFF_SMAX + TSEQ * DIM)         /* 24032 */
#define SMEM_BYTES (SMEM_FLOATS * 4)                /* 96128 */

// device scratch (no allocations allowed)
__device__ float g_embed[NSEQ * DIM];
__device__ float g_scores[NSEQ];
__device__ float g_bagmax[NBAGS];
__device__ float g_bagden[NBAGS];
__device__ float g_part[NBAGS * NCHUNK * DIM];

__device__ __forceinline__ float selu_f(float x) {
    const float s = 1.0507009873554805f;
    const float sa = 1.0507009873554805f * 1.6732632423543772f;
    float p = fmaxf(x, 0.f), m = fminf(x, 0.f);
    return fmaf(s, p, sa * (__expf(m) - 1.f));
}
__device__ __forceinline__ unsigned fmono(float x) {
    unsigned u = __float_as_uint(x);
    return (u & 0x80000000u) ? ~u : (u | 0x80000000u);
}
__device__ __forceinline__ float fmono_inv(unsigned u) {
    return (u & 0x80000000u) ? __uint_as_float(u ^ 0x80000000u)
                             : __uint_as_float(~u);
}
__device__ __forceinline__ unsigned tf32r(float x) {
    unsigned r;
    asm("cvt.rna.tf32.f32 %0, %1;" : "=r"(r) : "f"(x));
    return r;
}
__device__ __forceinline__ void mma8(float* c, unsigned a0, unsigned a1,
                                     unsigned a2, unsigned a3,
                                     unsigned b0, unsigned b1) {
    asm volatile(
        "mma.sync.aligned.m16n8k8.row.col.f32.tf32.tf32.f32 "
        "{%0,%1,%2,%3}, {%4,%5,%6,%7}, {%8,%9}, {%0,%1,%2,%3};\n"
        : "+f"(c[0]), "+f"(c[1]), "+f"(c[2]), "+f"(c[3])
        : "r"(a0), "r"(a1), "r"(a2), "r"(a3), "r"(b0), "r"(b1));
}

// ---------------------------------------------------------------------------
// Kernel A: conv1+conv2 as tf32 mma GEMMs + max-pool + attention MLP
// ---------------------------------------------------------------------------
__global__ __launch_bounds__(256, 2) void seq_kernel(
    const float* __restrict__ x,
    const float* __restrict__ w1, const float* __restrict__ b1,
    const float* __restrict__ w2, const float* __restrict__ b2,
    const float* __restrict__ aw1, const float* __restrict__ ab1,
    const float* __restrict__ aw2, const float* __restrict__ ab2,
    const float* __restrict__ aw3, const float* __restrict__ ab3)
{
    extern __shared__ float sm[];
    float* xs  = sm + OFF_XS;
    float* h1s = sm + OFF_H1;
    float* Bf1 = sm + OFF_BF1;
    float* Bf2 = sm + OFF_BF2;
    float* b1s = sm + OFF_B1;
    float* b2s = sm + OFF_B2;
    unsigned* smax = (unsigned*)(sm + OFF_SMAX);

    const int tid = threadIdx.x;
    const int warp = tid >> 5, lane = tid & 31;
    const int lr = lane >> 2, lc = lane & 3;

    // ---- stage inputs ----
    {
        const float4* xg = (const float4*)(x + (long)blockIdx.x * (TSEQ * LIN * CIN));
        float4* xs4 = (float4*)xs;
        #pragma unroll
        for (int i = tid; i < TSEQ * LIN * CIN / 4; i += 256) xs4[i] = xg[i];
    }
    for (int i = tid; i < 10 * 4 * 32; i += 256) {   // conv1 B fragments
        int ln = i & 31, nt = (i >> 5) & 3, ks = i >> 7;
        int k = ks * 8 + (ln & 3), n = nt * 8 + (ln >> 2);
        Bf1[2 * i]     = __uint_as_float(tf32r(w1[k * 32 + n]));
        Bf1[2 * i + 1] = __uint_as_float(tf32r(w1[(k + 4) * 32 + n]));
    }
    for (int i = tid; i < 16 * 4 * 32; i += 256) {   // conv2 B fragments
        int ln = i & 31, nt = (i >> 5) & 3, ks = i >> 7;
        int k = ks * 8 + (ln & 3), n = nt * 8 + (ln >> 2);
        Bf2[2 * i]     = __uint_as_float(tf32r(w2[k * 32 + n]));
        Bf2[2 * i + 1] = __uint_as_float(tf32r(w2[(k + 4) * 32 + n]));
    }
    if (tid < 32) { b1s[tid] = b1[tid]; b2s[tid] = b2[tid]; }
    smax[tid] = 0u;   // 256 slots == blockDim
    __syncthreads();

    // ---- conv1: rows = (seq,t), A = 80-float window of xs, B = Bf1 ----
    for (int tile = warp; tile < T1; tile += 8) {
        const int r0 = tile * 16 + lr, r1 = r0 + 8;
        const int s0 = r0 / L1OUT, t0 = r0 - s0 * L1OUT;
        const int s1 = r1 / L1OUT, t1 = r1 - s1 * L1OUT;
        const bool v0 = r0 < R1, v1 = r1 < R1;
        const float* A0 = xs + s0 * (LIN * CIN) + t0 * CIN + lc;
        const float* A1 = xs + s1 * (LIN * CIN) + t1 * CIN + lc;
        float acc[4][4];
        #pragma unroll
        for (int nt = 0; nt < 4; ++nt) {
            float bb0 = b1s[nt * 8 + 2 * lc], bb1 = b1s[nt * 8 + 2 * lc + 1];
            acc[nt][0] = bb0; acc[nt][1] = bb1; acc[nt][2] = bb0; acc[nt][3] = bb1;
        }
        #pragma unroll
        for (int ks = 0; ks < 10; ++ks) {
            unsigned a0 = __float_as_uint(A0[ks * 8]);
            unsigned a1 = __float_as_uint(A1[ks * 8]);
            unsigned a2 = __float_as_uint(A0[ks * 8 + 4]);
            unsigned a3 = __float_as_uint(A1[ks * 8 + 4]);
            #pragma unroll
            for (int nt = 0; nt < 4; ++nt) {
                const float2 bb = *(const float2*)&Bf1[((ks * 4 + nt) * 32 + lane) * 2];
                mma8(acc[nt], a0, a1, a2, a3,
                     __float_as_uint(bb.x), __float_as_uint(bb.y));
            }
        }
        #pragma unroll
        for (int nt = 0; nt < 4; ++nt) {
            const int col = nt * 8 + 2 * lc;
            if (v0) {
                float* o = h1s + s0 * H1SEQ + t0 * H1STRIDE + col;
                o[0] = selu_f(acc[nt][0]); o[1] = selu_f(acc[nt][1]);
            }
            if (v1) {
                float* o = h1s + s1 * H1SEQ + t1 * H1STRIDE + col;
                o[0] = selu_f(acc[nt][2]); o[1] = selu_f(acc[nt][3]);
            }
        }
    }
    __syncthreads();

    // ---- conv2: rows = (seq,p), A = 128-float window of h1 (tap-strided) ----
    for (int tile = warp; tile < T2; tile += 8) {
        const int r0 = tile * 16 + lr, r1 = r0 + 8;
        const int s0 = r0 / L2OUT, p0 = r0 - s0 * L2OUT;
        const int s1 = r1 / L2OUT, p1 = r1 - s1 * L2OUT;
        const float* A0 = h1s + s0 * H1SEQ + p0 * H1STRIDE + lc;
        const float* A1 = h1s + s1 * H1SEQ + p1 * H1STRIDE + lc;
        float acc[4][4];
        #pragma unroll
        for (int nt = 0; nt < 4; ++nt) {
            float bb0 = b2s[nt * 8 + 2 * lc], bb1 = b2s[nt * 8 + 2 * lc + 1];
            acc[nt][0] = bb0; acc[nt][1] = bb1; acc[nt][2] = bb0; acc[nt][3] = bb1;
        }
        #pragma unroll
        for (int ks = 0; ks < 16; ++ks) {
            const int off = (ks >> 2) * H1STRIDE + (ks & 3) * 8;
            unsigned a0 = __float_as_uint(A0[off]);
            unsigned a1 = __float_as_uint(A1[off]);
            unsigned a2 = __float_as_uint(A0[off + 4]);
            unsigned a3 = __float_as_uint(A1[off + 4]);
            #pragma unroll
            for (int nt = 0; nt < 4; ++nt) {
                const float2 bb = *(const float2*)&Bf2[((ks * 4 + nt) * 32 + lane) * 2];
                mma8(acc[nt], a0, a1, a2, a3,
                     __float_as_uint(bb.x), __float_as_uint(bb.y));
            }
        }
        #pragma unroll
        for (int nt = 0; nt < 4; ++nt) {
            const int col = nt * 8 + 2 * lc;
            atomicMax(&smax[s0 * DIM + col],     fmono(selu_f(acc[nt][0])));
            atomicMax(&smax[s0 * DIM + col + 1], fmono(selu_f(acc[nt][1])));
            atomicMax(&smax[s1 * DIM + col],     fmono(selu_f(acc[nt][2])));
            atomicMax(&smax[s1 * DIM + col + 1], fmono(selu_f(acc[nt][3])));
        }
    }
    __syncthreads();

    // decode monotonic max -> embeddings (in place)
    float* es = (float*)smax;
    { unsigned u = smax[tid]; __syncthreads(); es[tid] = fmono_inv(u); }
    __syncthreads();

    // ---- attention MLP: warp w -> sequence w ----
    const float* e = es + warp * DIM;
    const int j = lane;

    float a1v = __ldg(&ab1[j]);
    #pragma unroll 8
    for (int i = 0; i < DIM; ++i)
        a1v = fmaf(e[i], __ldg(&aw1[i * DIM + j]), a1v);
    a1v = selu_f(a1v);

    float a2v = __ldg(&ab2[j]);
    #pragma unroll 8
    for (int i = 0; i < DIM; ++i)
        a2v = fmaf(__shfl_sync(0xffffffffu, a1v, i), __ldg(&aw2[i * DIM + j]), a2v);
    a2v = selu_f(a2v);

    float sc = a2v * __ldg(&aw3[j]);
    #pragma unroll
    for (int o = 16; o > 0; o >>= 1) sc += __shfl_xor_sync(0xffffffffu, sc, o);

    const long n = (long)blockIdx.x * TSEQ + warp;
    g_embed[n * DIM + j] = e[j];
    if (j == 0) g_scores[n] = sc + __ldg(&ab3[0]);
}

// ---------------------------------------------------------------------------
// B0: per-bag score max + denom (100 blocks)
// ---------------------------------------------------------------------------
__global__ __launch_bounds__(256) void bag_stats_kernel(const int* __restrict__ nper)
{
    __shared__ float red[256];
    __shared__ int s_off, s_cnt;
    __shared__ float s_max;
    const int tid = threadIdx.x, b = blockIdx.x;
    if (tid == 0) {
        int off = 0;
        for (int i = 0; i < b; ++i) off += nper[i];
        s_off = off; s_cnt = nper[b];
    }
    __syncthreads();
    const int off = s_off, cnt = s_cnt;

    float lm = -INFINITY;
    for (int i = tid; i < cnt; i += 256) lm = fmaxf(lm, g_scores[off + i]);
    red[tid] = lm; __syncthreads();
    for (int s = 128; s > 0; s >>= 1) {
        if (tid < s) red[tid] = fmaxf(red[tid], red[tid + s]);
        __syncthreads();
    }
    if (tid == 0) s_max = red[0];
    __syncthreads();
    const float mx = s_max;

    float ls = 0.f;
    for (int i = tid; i < cnt; i += 256) ls += __expf(g_scores[off + i] - mx);
    red[tid] = ls; __syncthreads();
    for (int s = 128; s > 0; s >>= 1) {
        if (tid < s) red[tid] += red[tid + s];
        __syncthreads();
    }
    if (tid == 0) { g_bagmax[b] = mx; g_bagden[b] = red[0]; }
}

// ---------------------------------------------------------------------------
// B1: partial weighted pooling (NBAGS*NCHUNK blocks)
// ---------------------------------------------------------------------------
__global__ __launch_bounds__(256) void bag_pool_kernel(const int* __restrict__ nper)
{
    __shared__ float part[8][DIM];
    __shared__ int s_off, s_cnt;
    const int tid = threadIdx.x;
    const int b = blockIdx.x / NCHUNK, j = blockIdx.x % NCHUNK;
    if (tid == 0) {
        int off = 0;
        for (int i = 0; i < b; ++i) off += nper[i];
        s_off = off; s_cnt = nper[b];
    }
    __syncthreads();
    const int off = s_off, cnt = s_cnt;
    const int chunk = (cnt + NCHUNK - 1) / NCHUNK;
    const int p0 = j * chunk, p1 = min(p0 + chunk, cnt);
    const float mx = g_bagmax[b];

    const int g = tid >> 5, c = tid & 31;
    float acc = 0.f;
    for (int p = p0 + g; p < p1; p += 8) {
        const float wgt = __expf(g_scores[off + p] - mx);
        acc = fmaf(wgt, g_embed[(long)(off + p) * DIM + c], acc);
    }
    part[g][c] = acc;
    __syncthreads();
    if (tid < DIM) {
        float s = 0.f;
        #pragma unroll
        for (int gg = 0; gg < 8; ++gg) s += part[gg][tid];
        g_part[(b * NCHUNK + j) * DIM + tid] = s;
    }
}

// ---------------------------------------------------------------------------
// B2: combine partials + output heads (100 blocks, 128 threads)
// ---------------------------------------------------------------------------
__global__ __launch_bounds__(128) void bag_head_kernel(
    const float* __restrict__ oaw1, const float* __restrict__ oab1,
    const float* __restrict__ oaw2, const float* __restrict__ oab2,
    const float* __restrict__ obw1, const float* __restrict__ obb1,
    const float* __restrict__ obw2, const float* __restrict__ obb2,
    float* __restrict__ out)
{
    __shared__ float pooled[DIM];
    __shared__ float hA[DIM], hB[DIM];
    const int tid = threadIdx.x, b = blockIdx.x;

    if (tid < DIM) {
        float s = 0.f;
        #pragma unroll
        for (int j = 0; j < NCHUNK; ++j) s += g_part[(b * NCHUNK + j) * DIM + tid];
        pooled[tid] = s / g_bagden[b];
    }
    __syncthreads();

    if (tid < DIM) {
        float v = __ldg(&oab1[tid]);
        #pragma unroll 8
        for (int i = 0; i < DIM; ++i) v = fmaf(pooled[i], __ldg(&oaw1[i * DIM + tid]), v);
        hA[tid] = selu_f(v);
    } else if (tid < 2 * DIM) {
        const int k = tid - DIM;
        float v = __ldg(&obb1[k]);
        #pragma unroll 8
        for (int i = 0; i < DIM; ++i) v = fmaf(pooled[i], __ldg(&obw1[i * DIM + k]), v);
        hB[k] = selu_f(v);
    }
    __syncthreads();

    if (tid < 21) {
        float v = __ldg(&oab2[tid]);
        #pragma unroll 8
        for (int i = 0; i < DIM; ++i) v = fmaf(hA[i], __ldg(&oaw2[i * 21 + tid]), v);
        out[b * 21 + tid] = 1.f / (1.f + __expf(-v));
    } else if (tid >= 64 && tid < 104) {
        const int k = tid - 64;
        float v = __ldg(&obb2[k]);
        #pragma unroll 8
        for (int i = 0; i < DIM; ++i) v = fmaf(hB[i], __ldg(&obw2[i * 40 + k]), v);
        out[NBAGS * 21 + b * 40 + k] = 1.f / (1.f + __expf(-v));
    }
}

extern "C" void kernel_launch(void* const* d_in, const int* in_sizes, int n_in,
                              void* d_out, int out_size)
{
    (void)in_sizes; (void)n_in; (void)out_size;
    const float* x    = (const float*)d_in[0];
    const int*   nper = (const int*)  d_in[1];
    const float* w1   = (const float*)d_in[2];
    const float* b1   = (const float*)d_in[3];
    const float* w2   = (const float*)d_in[4];
    const float* b2   = (const float*)d_in[5];
    const float* aw1  = (const float*)d_in[6];
    const float* ab1  = (const float*)d_in[7];
    const float* aw2  = (const float*)d_in[8];
    const float* ab2  = (const float*)d_in[9];
    const float* aw3  = (const float*)d_in[10];
    const float* ab3  = (const float*)d_in[11];
    const float* oaw1 = (const float*)d_in[12];
    const float* oab1 = (const float*)d_in[13];
    const float* oaw2 = (const float*)d_in[14];
    const float* oab2 = (const float*)d_in[15];
    const float* obw1 = (const float*)d_in[16];
    const float* obb1 = (const float*)d_in[17];
    const float* obw2 = (const float*)d_in[18];
    const float* obb2 = (const float*)d_in[19];

    cudaFuncSetAttribute(seq_kernel, cudaFuncAttributeMaxDynamicSharedMemorySize,
                         SMEM_BYTES);
    seq_kernel<<<NBLK, 256, SMEM_BYTES>>>(
        x, w1, b1, w2, b2, aw1, ab1, aw2, ab2, aw3, ab3);
    bag_stats_kernel<<<NBAGS, 256>>>(nper);
    bag_pool_kernel<<<NBAGS * NCHUNK, 256>>>(nper);
    bag_head_kernel<<<NBAGS, 128>>>(
        oaw1, oab1, oaw2, oab2, obw1, obb1, obw2, obb2, (float*)d_out);
}

// round 3
// speedup vs baseline: 4.3048x; 1.0540x over previous
#include <cuda_runtime.h>
#include <cuda_bf16.h>
#include <math.h>

#define NSEQ 250000
#define LIN 40
#define CIN 20
#define DIM 32
#define L1OUT 37
#define L2OUT 34
#define NBAGS 100
#define TSEQ 8
#define NBLK (NSEQ / TSEQ)      /* 31250 */
#define R1 (TSEQ * L1OUT)       /* 296 */
#define R2 (TSEQ * L2OUT)       /* 272 */
#define T1 ((R1 + 15) / 16)     /* 19 */
#define T2 (R2 / 16)            /* 17 */
#define XSEQ (LIN * CIN)        /* 800 */
#define H1ROW 40                /* padded h1 row (bf16): bank-conflict-free */
#define H1SEQ (L1OUT * H1ROW)   /* 1480 */

__device__ float g_embed[NSEQ * DIM];
__device__ float g_scores[NSEQ];

__device__ __forceinline__ float selu_f(float x) {
    const float s = 1.0507009873554805f;
    const float sa = 1.0507009873554805f * 1.6732632423543772f;
    float p = fmaxf(x, 0.f), m = fminf(x, 0.f);
    return fmaf(s, p, sa * (__expf(m) - 1.f));
}
__device__ __forceinline__ unsigned fmono(float x) {
    unsigned u = __float_as_uint(x);
    return (u & 0x80000000u) ? ~u : (u | 0x80000000u);
}
__device__ __forceinline__ float fmono_inv(unsigned u) {
    return (u & 0x80000000u) ? __uint_as_float(u ^ 0x80000000u)
                             : __uint_as_float(~u);
}
__device__ __forceinline__ unsigned pk(float lo, float hi) {
    __nv_bfloat162 t = __floats2bfloat162_rn(lo, hi);  // .x = lo (low 16 bits)
    return *reinterpret_cast<unsigned*>(&t);
}
__device__ __forceinline__ void mma16(float* c, unsigned a0, unsigned a1,
                                      unsigned a2, unsigned a3,
                                      unsigned b0, unsigned b1) {
    asm volatile(
        "mma.sync.aligned.m16n8k16.row.col.f32.bf16.bf16.f32 "
        "{%0,%1,%2,%3}, {%4,%5,%6,%7}, {%8,%9}, {%0,%1,%2,%3};\n"
        : "+f"(c[0]), "+f"(c[1]), "+f"(c[2]), "+f"(c[3])
        : "r"(a0), "r"(a1), "r"(a2), "r"(a3), "r"(b0), "r"(b1));
}

__global__ void nop_kernel() {}

// ---------------------------------------------------------------------------
// Kernel A: conv1+conv2 as bf16 mma GEMMs + max-pool + attention MLP
// ---------------------------------------------------------------------------
__global__ __launch_bounds__(256, 2) void seq_kernel(
    const float* __restrict__ x,
    const float* __restrict__ w1, const float* __restrict__ b1,
    const float* __restrict__ w2, const float* __restrict__ b2,
    const float* __restrict__ aw1, const float* __restrict__ ab1,
    const float* __restrict__ aw2, const float* __restrict__ ab2,
    const float* __restrict__ aw3, const float* __restrict__ ab3)
{
    __shared__ __nv_bfloat16 xs[TSEQ * XSEQ];    // 12.8 KB
    __shared__ __nv_bfloat16 h1s[TSEQ * H1SEQ];  // 23.7 KB
    __shared__ float b1s[DIM], b2s[DIM];
    __shared__ unsigned smax[256];

    const int tid = threadIdx.x;
    const int warp = tid >> 5, lane = tid & 31;
    const int lr = lane >> 2, lc = lane & 3;

    // ---- stage x as bf16 (flat copy, contiguous) ----
    {
        const float4* xg = (const float4*)(x + (long)blockIdx.x * (TSEQ * XSEQ));
        uint2* xs2 = (uint2*)xs;
        #pragma unroll
        for (int i = tid; i < TSEQ * XSEQ / 4; i += 256) {
            const float4 v = xg[i];
            xs2[i] = make_uint2(pk(v.x, v.y), pk(v.z, v.w));
        }
    }
    if (tid < DIM) { b1s[tid] = b1[tid]; b2s[tid] = b2[tid]; }
    smax[tid] = 0u;

    // ---- conv1 B fragments -> registers (k16 bf16 layout) ----
    unsigned B1r[5][4][2];
    #pragma unroll
    for (int ks = 0; ks < 5; ++ks)
        #pragma unroll
        for (int nt = 0; nt < 4; ++nt) {
            const int k0 = 16 * ks + 2 * lc, n = 8 * nt + lr;
            B1r[ks][nt][0] = pk(__ldg(&w1[k0 * 32 + n]), __ldg(&w1[(k0 + 1) * 32 + n]));
            B1r[ks][nt][1] = pk(__ldg(&w1[(k0 + 8) * 32 + n]), __ldg(&w1[(k0 + 9) * 32 + n]));
        }
    __syncthreads();

    // ---- conv1: row r=(s,t): A = 80 contiguous bf16 window of xs ----
    for (int tile = warp; tile < T1; tile += 8) {
        const int r0 = tile * 16 + lr, r1 = r0 + 8;
        const bool v0 = r0 < R1, v1 = r1 < R1;
        const int s0 = v0 ? r0 / L1OUT : 0, t0 = v0 ? r0 - (r0 / L1OUT) * L1OUT : 0;
        const int s1 = v1 ? r1 / L1OUT : 0, t1 = v1 ? r1 - (r1 / L1OUT) * L1OUT : 0;
        const __nv_bfloat16* A0 = xs + s0 * XSEQ + t0 * CIN;
        const __nv_bfloat16* A1 = xs + s1 * XSEQ + t1 * CIN;
        float acc[4][4];
        #pragma unroll
        for (int nt = 0; nt < 4; ++nt) {
            const float bb0 = b1s[nt * 8 + 2 * lc], bb1 = b1s[nt * 8 + 2 * lc + 1];
            acc[nt][0] = bb0; acc[nt][1] = bb1; acc[nt][2] = bb0; acc[nt][3] = bb1;
        }
        #pragma unroll
        for (int ks = 0; ks < 5; ++ks) {
            const int k0 = 16 * ks + 2 * lc;
            const unsigned a0 = *(const unsigned*)(A0 + k0);
            const unsigned a1 = *(const unsigned*)(A1 + k0);
            const unsigned a2 = *(const unsigned*)(A0 + k0 + 8);
            const unsigned a3 = *(const unsigned*)(A1 + k0 + 8);
            #pragma unroll
            for (int nt = 0; nt < 4; ++nt)
                mma16(acc[nt], a0, a1, a2, a3, B1r[ks][nt][0], B1r[ks][nt][1]);
        }
        #pragma unroll
        for (int nt = 0; nt < 4; ++nt) {
            const int col = nt * 8 + 2 * lc;
            if (v0) *(unsigned*)(h1s + s0 * H1SEQ + t0 * H1ROW + col) =
                        pk(selu_f(acc[nt][0]), selu_f(acc[nt][1]));
            if (v1) *(unsigned*)(h1s + s1 * H1SEQ + t1 * H1ROW + col) =
                        pk(selu_f(acc[nt][2]), selu_f(acc[nt][3]));
        }
    }

    // ---- conv2 B fragments -> registers ----
    unsigned B2r[8][4][2];
    #pragma unroll
    for (int ks = 0; ks < 8; ++ks)
        #pragma unroll
        for (int nt = 0; nt < 4; ++nt) {
            const int k0 = 16 * ks + 2 * lc, n = 8 * nt + lr;
            B2r[ks][nt][0] = pk(__ldg(&w2[k0 * 32 + n]), __ldg(&w2[(k0 + 1) * 32 + n]));
            B2r[ks][nt][1] = pk(__ldg(&w2[(k0 + 8) * 32 + n]), __ldg(&w2[(k0 + 9) * 32 + n]));
        }
    __syncthreads();

    // ---- conv2: row r=(s,p): A col k -> h1[s, p + k/32, k%32] ----
    for (int tile = warp; tile < T2; tile += 8) {
        const int r0 = tile * 16 + lr, r1 = r0 + 8;   // always < 272
        const int s0 = r0 / L2OUT, p0 = r0 - s0 * L2OUT;
        const int s1 = r1 / L2OUT, p1 = r1 - s1 * L2OUT;
        const __nv_bfloat16* A0 = h1s + s0 * H1SEQ + p0 * H1ROW;
        const __nv_bfloat16* A1 = h1s + s1 * H1SEQ + p1 * H1ROW;
        float acc[4][4];
        #pragma unroll
        for (int nt = 0; nt < 4; ++nt) {
            const float bb0 = b2s[nt * 8 + 2 * lc], bb1 = b2s[nt * 8 + 2 * lc + 1];
            acc[nt][0] = bb0; acc[nt][1] = bb1; acc[nt][2] = bb0; acc[nt][3] = bb1;
        }
        #pragma unroll
        for (int ks = 0; ks < 8; ++ks) {
            const int off = (ks >> 1) * H1ROW + (ks & 1) * 16 + 2 * lc;
            const unsigned a0 = *(const unsigned*)(A0 + off);
            const unsigned a1 = *(const unsigned*)(A1 + off);
            const unsigned a2 = *(const unsigned*)(A0 + off + 8);
            const unsigned a3 = *(const unsigned*)(A1 + off + 8);
            #pragma unroll
            for (int nt = 0; nt < 4; ++nt)
                mma16(acc[nt], a0, a1, a2, a3, B2r[ks][nt][0], B2r[ks][nt][1]);
        }
        #pragma unroll
        for (int nt = 0; nt < 4; ++nt) {
            const int col = nt * 8 + 2 * lc;
            atomicMax(&smax[s0 * DIM + col],     fmono(selu_f(acc[nt][0])));
            atomicMax(&smax[s0 * DIM + col + 1], fmono(selu_f(acc[nt][1])));
            atomicMax(&smax[s1 * DIM + col],     fmono(selu_f(acc[nt][2])));
            atomicMax(&smax[s1 * DIM + col + 1], fmono(selu_f(acc[nt][3])));
        }
    }
    __syncthreads();

    // decode monotonic max -> embeddings (in place)
    float* es = (float*)smax;
    { const unsigned u = smax[tid]; __syncthreads(); es[tid] = fmono_inv(u); }
    __syncthreads();

    // ---- attention MLP: warp w -> sequence w ----
    const float* e = es + warp * DIM;
    const int j = lane;

    float a1v = __ldg(&ab1[j]);
    #pragma unroll 8
    for (int i = 0; i < DIM; ++i)
        a1v = fmaf(e[i], __ldg(&aw1[i * DIM + j]), a1v);
    a1v = selu_f(a1v);

    float a2v = __ldg(&ab2[j]);
    #pragma unroll 8
    for (int i = 0; i < DIM; ++i)
        a2v = fmaf(__shfl_sync(0xffffffffu, a1v, i), __ldg(&aw2[i * DIM + j]), a2v);
    a2v = selu_f(a2v);

    float sc = a2v * __ldg(&aw3[j]);
    #pragma unroll
    for (int o = 16; o > 0; o >>= 1) sc += __shfl_xor_sync(0xffffffffu, sc, o);

    const long n = (long)blockIdx.x * TSEQ + warp;
    g_embed[n * DIM + j] = e[j];
    if (j == 0) g_scores[n] = sc + __ldg(&ab3[0]);
}

// ---------------------------------------------------------------------------
// Kernel B: whole bag pipeline in one kernel (100 blocks x 1024 threads)
// ---------------------------------------------------------------------------
__global__ __launch_bounds__(1024) void bag_all_kernel(
    const int* __restrict__ nper,
    const float* __restrict__ oaw1, const float* __restrict__ oab1,
    const float* __restrict__ oaw2, const float* __restrict__ oab2,
    const float* __restrict__ obw1, const float* __restrict__ obb1,
    const float* __restrict__ obw2, const float* __restrict__ obb2,
    float* __restrict__ out)
{
    __shared__ float red[1024];
    __shared__ float part[32][33];
    __shared__ float pooled[DIM], hA[DIM], hB[DIM];
    __shared__ int s_off, s_cnt;
    __shared__ float s_mx, s_dn;

    const int tid = threadIdx.x, b = blockIdx.x;
    if (tid == 0) {
        int off = 0;
        for (int i = 0; i < b; ++i) off += nper[i];
        s_off = off; s_cnt = nper[b];
    }
    __syncthreads();
    const int off = s_off, cnt = s_cnt;

    // segment max
    float lm = -INFINITY;
    for (int i = tid; i < cnt; i += 1024) lm = fmaxf(lm, g_scores[off + i]);
    red[tid] = lm; __syncthreads();
    for (int s = 512; s > 0; s >>= 1) {
        if (tid < s) red[tid] = fmaxf(red[tid], red[tid + s]);
        __syncthreads();
    }
    if (tid == 0) s_mx = red[0];
    __syncthreads();
    const float mx = s_mx;

    // segment sum of exp
    float ls = 0.f;
    for (int i = tid; i < cnt; i += 1024) ls += __expf(g_scores[off + i] - mx);
    red[tid] = ls; __syncthreads();
    for (int s = 512; s > 0; s >>= 1) {
        if (tid < s) red[tid] += red[tid + s];
        __syncthreads();
    }
    if (tid == 0) s_dn = red[0];
    __syncthreads();
    const float dn = s_dn;

    // weighted pooling: 32 warps, lane = channel
    const int g = tid >> 5, c = tid & 31;
    float acc = 0.f;
    for (int p = g; p < cnt; p += 32) {
        const float wgt = __expf(g_scores[off + p] - mx);
        acc = fmaf(wgt, g_embed[(long)(off + p) * DIM + c], acc);
    }
    part[g][c] = acc;
    __syncthreads();
    if (tid < DIM) {
        float s = 0.f;
        #pragma unroll
        for (int gg = 0; gg < 32; ++gg) s += part[gg][tid];
        pooled[tid] = s / dn;
    }
    __syncthreads();

    // hidden layers of both heads
    if (tid < DIM) {
        float v = __ldg(&oab1[tid]);
        #pragma unroll 8
        for (int i = 0; i < DIM; ++i) v = fmaf(pooled[i], __ldg(&oaw1[i * DIM + tid]), v);
        hA[tid] = selu_f(v);
    } else if (tid < 2 * DIM) {
        const int k = tid - DIM;
        float v = __ldg(&obb1[k]);
        #pragma unroll 8
        for (int i = 0; i < DIM; ++i) v = fmaf(pooled[i], __ldg(&obw1[i * DIM + k]), v);
        hB[k] = selu_f(v);
    }
    __syncthreads();

    // final layers + sigmoid
    if (tid < 21) {
        float v = __ldg(&oab2[tid]);
        #pragma unroll 8
        for (int i = 0; i < DIM; ++i) v = fmaf(hA[i], __ldg(&oaw2[i * 21 + tid]), v);
        out[b * 21 + tid] = 1.f / (1.f + __expf(-v));
    } else if (tid >= 64 && tid < 104) {
        const int k = tid - 64;
        float v = __ldg(&obb2[k]);
        #pragma unroll 8
        for (int i = 0; i < DIM; ++i) v = fmaf(hB[i], __ldg(&obw2[i * 40 + k]), v);
        out[NBAGS * 21 + b * 40 + k] = 1.f / (1.f + __expf(-v));
    }
}

extern "C" void kernel_launch(void* const* d_in, const int* in_sizes, int n_in,
                              void* d_out, int out_size)
{
    (void)in_sizes; (void)n_in; (void)out_size;
    const float* x    = (const float*)d_in[0];
    const int*   nper = (const int*)  d_in[1];
    const float* w1   = (const float*)d_in[2];
    const float* b1   = (const float*)d_in[3];
    const float* w2   = (const float*)d_in[4];
    const float* b2   = (const float*)d_in[5];
    const float* aw1  = (const float*)d_in[6];
    const float* ab1  = (const float*)d_in[7];
    const float* aw2  = (const float*)d_in[8];
    const float* ab2  = (const float*)d_in[9];
    const float* aw3  = (const float*)d_in[10];
    const float* ab3  = (const float*)d_in[11];
    const float* oaw1 = (const float*)d_in[12];
    const float* oab1 = (const float*)d_in[13];
    const float* oaw2 = (const float*)d_in[14];
    const float* oab2 = (const float*)d_in[15];
    const float* obw1 = (const float*)d_in[16];
    const float* obb1 = (const float*)d_in[17];
    const float* obw2 = (const float*)d_in[18];
    const float* obb2 = (const float*)d_in[19];

    // 3 nops shift the ncu -s 5 capture window onto seq_kernel
    nop_kernel<<<1, 32>>>();
    nop_kernel<<<1, 32>>>();
    nop_kernel<<<1, 32>>>();
    seq_kernel<<<NBLK, 256>>>(
        x, w1, b1, w2, b2, aw1, ab1, aw2, ab2, aw3, ab3);
    bag_all_kernel<<<NBAGS, 1024>>>(
        nper, oaw1, oab1, oaw2, oab2, obw1, obb1, obw2, obb2, (float*)d_out);
}

// round 4
// speedup vs baseline: 5.0177x; 1.1656x over previous
#include <cuda_runtime.h>
#include <cuda_bf16.h>
#include <math.h>

#define NSEQ 250000
#define LIN 40
#define CIN 20
#define DIM 32
#define L1OUT 37
#define L2OUT 34
#define NBAGS 100
#define TSEQ 8
#define NBLK (NSEQ / TSEQ)      /* 31250 */
#define XROW 24                 /* padded x row (bf16 elems): conflict-free */
#define XSEQ (LIN * XROW)       /* 960 */
#define H1ROW 40                /* padded h1 row: banks (20lr+lc) distinct */
#define H1SEQ (L1OUT * H1ROW)   /* 1480 */

__device__ float g_embed[NSEQ * DIM];
__device__ float g_scores[NSEQ];

__device__ __forceinline__ float selu_f(float x) {
    const float s = 1.0507009873554805f;
    const float sa = 1.0507009873554805f * 1.6732632423543772f;
    float p = fmaxf(x, 0.f), m = fminf(x, 0.f);
    return fmaf(s, p, sa * (__expf(m) - 1.f));
}
__device__ __forceinline__ unsigned pk(float lo, float hi) {
    __nv_bfloat162 t = __floats2bfloat162_rn(lo, hi);  // .x = lo
    return *reinterpret_cast<unsigned*>(&t);
}
__device__ __forceinline__ void mma16(float* c, unsigned a0, unsigned a1,
                                      unsigned a2, unsigned a3,
                                      unsigned b0, unsigned b1) {
    asm volatile(
        "mma.sync.aligned.m16n8k16.row.col.f32.bf16.bf16.f32 "
        "{%0,%1,%2,%3}, {%4,%5,%6,%7}, {%8,%9}, {%0,%1,%2,%3};\n"
        : "+f"(c[0]), "+f"(c[1]), "+f"(c[2]), "+f"(c[3])
        : "r"(a0), "r"(a1), "r"(a2), "r"(a3), "r"(b0), "r"(b1));
}

__global__ void nop_kernel() {}

// w1 padded lookup: padded k index kp -> tap = kp/24, ch = kp%24 (ch>=20 -> 0)
__device__ __forceinline__ float w1pad(const float* __restrict__ w1, int kp, int n) {
    const int tap = kp / 24, ch = kp - tap * 24;
    return (ch < 20) ? __ldg(&w1[(tap * 20 + ch) * 32 + n]) : 0.f;
}

// ---------------------------------------------------------------------------
// Kernel A: per-seq warp-owned conv1+conv2 (bf16 mma) + max + attention MLP
// ---------------------------------------------------------------------------
__global__ __launch_bounds__(256, 2) void seq_kernel(
    const float* __restrict__ x,
    const float* __restrict__ w1, const float* __restrict__ b1,
    const float* __restrict__ w2, const float* __restrict__ b2,
    const float* __restrict__ aw1, const float* __restrict__ ab1,
    const float* __restrict__ aw2, const float* __restrict__ ab2,
    const float* __restrict__ aw3, const float* __restrict__ ab3)
{
    __shared__ __nv_bfloat16 xs[TSEQ * XSEQ];    // 15.4 KB
    __shared__ __nv_bfloat16 h1s[TSEQ * H1SEQ];  // 23.7 KB
    __shared__ float es_s[TSEQ][DIM];            // 1 KB

    const int tid = threadIdx.x;
    const int warp = tid >> 5, lane = tid & 31;
    const int lr = lane >> 2, lc = lane & 3;

    // ---- stage x -> padded bf16 rows (chunks of 4 never straddle rows) ----
    {
        const float4* xg = (const float4*)(x + (long)blockIdx.x * (TSEQ * LIN * CIN));
        #pragma unroll
        for (int i = tid; i < TSEQ * LIN * CIN / 4; i += 256) {
            const float4 v = xg[i];
            const int e = 4 * i, row = e / 20, ch = e - row * 20;
            *(uint2*)(xs + row * XROW + ch) =
                make_uint2(pk(v.x, v.y), pk(v.z, v.w));
        }
        #pragma unroll
        for (int i = tid; i < TSEQ * LIN; i += 256)          // zero pads
            *(uint2*)(xs + i * XROW + 20) = make_uint2(0u, 0u);
    }

    // ---- conv1 B fragments (K=96 zero-padded) + biases -> registers ----
    unsigned B1r[6][4][2];
    #pragma unroll
    for (int ks = 0; ks < 6; ++ks)
        #pragma unroll
        for (int nt = 0; nt < 4; ++nt) {
            const int kp = 16 * ks + 2 * lc, n = 8 * nt + lr;
            B1r[ks][nt][0] = pk(w1pad(w1, kp, n),     w1pad(w1, kp + 1, n));
            B1r[ks][nt][1] = pk(w1pad(w1, kp + 8, n), w1pad(w1, kp + 9, n));
        }
    float bias1[4][2];
    #pragma unroll
    for (int nt = 0; nt < 4; ++nt) {
        bias1[nt][0] = __ldg(&b1[nt * 8 + 2 * lc]);
        bias1[nt][1] = __ldg(&b1[nt * 8 + 2 * lc + 1]);
    }
    __syncthreads();

    const __nv_bfloat16* Xw = xs + warp * XSEQ;
    __nv_bfloat16* Hw = h1s + warp * H1SEQ;

    // ---- conv1: 3 fixed m16 tiles per sequence (rows clamped to 36) ----
    #pragma unroll
    for (int tile = 0; tile < 3; ++tile) {
        const int t0 = tile * 16 + lr;
        const int t0c = t0 > 36 ? 36 : t0;
        const int t1c = (t0 + 8) > 36 ? 36 : (t0 + 8);
        const __nv_bfloat16* A0 = Xw + t0c * XROW + 2 * lc;
        const __nv_bfloat16* A1 = Xw + t1c * XROW + 2 * lc;
        float acc[4][4];
        #pragma unroll
        for (int nt = 0; nt < 4; ++nt) {
            acc[nt][0] = bias1[nt][0]; acc[nt][1] = bias1[nt][1];
            acc[nt][2] = bias1[nt][0]; acc[nt][3] = bias1[nt][1];
        }
        #pragma unroll
        for (int ks = 0; ks < 6; ++ks) {
            const unsigned a0 = *(const unsigned*)(A0 + 16 * ks);
            const unsigned a1 = *(const unsigned*)(A1 + 16 * ks);
            const unsigned a2 = *(const unsigned*)(A0 + 16 * ks + 8);
            const unsigned a3 = *(const unsigned*)(A1 + 16 * ks + 8);
            #pragma unroll
            for (int nt = 0; nt < 4; ++nt)
                mma16(acc[nt], a0, a1, a2, a3, B1r[ks][nt][0], B1r[ks][nt][1]);
        }
        #pragma unroll
        for (int nt = 0; nt < 4; ++nt) {
            const int col = nt * 8 + 2 * lc;
            if (tile < 2) {
                *(unsigned*)(Hw + t0 * H1ROW + col) =
                    pk(selu_f(acc[nt][0]), selu_f(acc[nt][1]));
                *(unsigned*)(Hw + (t0 + 8) * H1ROW + col) =
                    pk(selu_f(acc[nt][2]), selu_f(acc[nt][3]));
            } else if (lr < 5) {   // rows 32..36 only, once each
                *(unsigned*)(Hw + t0 * H1ROW + col) =
                    pk(selu_f(acc[nt][0]), selu_f(acc[nt][1]));
            }
        }
    }

    // ---- conv2 B fragments + biases ----
    unsigned B2r[8][4][2];
    #pragma unroll
    for (int ks = 0; ks < 8; ++ks)
        #pragma unroll
        for (int nt = 0; nt < 4; ++nt) {
            const int k0 = 16 * ks + 2 * lc, n = 8 * nt + lr;
            B2r[ks][nt][0] = pk(__ldg(&w2[k0 * 32 + n]), __ldg(&w2[(k0 + 1) * 32 + n]));
            B2r[ks][nt][1] = pk(__ldg(&w2[(k0 + 8) * 32 + n]), __ldg(&w2[(k0 + 9) * 32 + n]));
        }
    float bias2[4][2];
    #pragma unroll
    for (int nt = 0; nt < 4; ++nt) {
        bias2[nt][0] = __ldg(&b2[nt * 8 + 2 * lc]);
        bias2[nt][1] = __ldg(&b2[nt * 8 + 2 * lc + 1]);
    }
    __syncwarp();   // h1 rows for this seq written by this warp only

    // ---- conv2: 3 fixed tiles, raw-acc max (selu deferred: monotonic) ----
    float vm[4][2];
    #pragma unroll
    for (int nt = 0; nt < 4; ++nt) { vm[nt][0] = -INFINITY; vm[nt][1] = -INFINITY; }

    #pragma unroll
    for (int tile = 0; tile < 3; ++tile) {
        const int p0 = tile * 16 + lr;
        const int p0c = p0 > 33 ? 33 : p0;
        const int p1c = (p0 + 8) > 33 ? 33 : (p0 + 8);
        const __nv_bfloat16* A0 = Hw + p0c * H1ROW + 2 * lc;
        const __nv_bfloat16* A1 = Hw + p1c * H1ROW + 2 * lc;
        float acc[4][4];
        #pragma unroll
        for (int nt = 0; nt < 4; ++nt) {
            acc[nt][0] = bias2[nt][0]; acc[nt][1] = bias2[nt][1];
            acc[nt][2] = bias2[nt][0]; acc[nt][3] = bias2[nt][1];
        }
        #pragma unroll
        for (int ks = 0; ks < 8; ++ks) {
            const int off = (ks >> 1) * H1ROW + (ks & 1) * 16;
            const unsigned a0 = *(const unsigned*)(A0 + off);
            const unsigned a1 = *(const unsigned*)(A1 + off);
            const unsigned a2 = *(const unsigned*)(A0 + off + 8);
            const unsigned a3 = *(const unsigned*)(A1 + off + 8);
            #pragma unroll
            for (int nt = 0; nt < 4; ++nt)
                mma16(acc[nt], a0, a1, a2, a3, B2r[ks][nt][0], B2r[ks][nt][1]);
        }
        #pragma unroll
        for (int nt = 0; nt < 4; ++nt) {
            vm[nt][0] = fmaxf(vm[nt][0], acc[nt][0]);
            vm[nt][1] = fmaxf(vm[nt][1], acc[nt][1]);
            if (tile < 2) {   // tile2 r1 rows are pure dups of row 33
                vm[nt][0] = fmaxf(vm[nt][0], acc[nt][2]);
                vm[nt][1] = fmaxf(vm[nt][1], acc[nt][3]);
            }
        }
    }

    // reduce max over lr lanes (bits 2,3,4); then selu on 32 survivors
    #pragma unroll
    for (int nt = 0; nt < 4; ++nt)
        #pragma unroll
        for (int j = 0; j < 2; ++j) {
            float v = vm[nt][j];
            v = fmaxf(v, __shfl_xor_sync(0xffffffffu, v, 4));
            v = fmaxf(v, __shfl_xor_sync(0xffffffffu, v, 8));
            v = fmaxf(v, __shfl_xor_sync(0xffffffffu, v, 16));
            vm[nt][j] = v;
        }
    if (lane < 4) {
        #pragma unroll
        for (int nt = 0; nt < 4; ++nt) {
            es_s[warp][nt * 8 + 2 * lane]     = selu_f(vm[nt][0]);
            es_s[warp][nt * 8 + 2 * lane + 1] = selu_f(vm[nt][1]);
        }
    }
    __syncwarp();

    // ---- attention MLP: warp w -> sequence w ----
    const float* e = es_s[warp];
    const int j = lane;

    float a1v = __ldg(&ab1[j]);
    #pragma unroll 8
    for (int i = 0; i < DIM; ++i)
        a1v = fmaf(e[i], __ldg(&aw1[i * DIM + j]), a1v);
    a1v = selu_f(a1v);

    float a2v = __ldg(&ab2[j]);
    #pragma unroll 8
    for (int i = 0; i < DIM; ++i)
        a2v = fmaf(__shfl_sync(0xffffffffu, a1v, i), __ldg(&aw2[i * DIM + j]), a2v);
    a2v = selu_f(a2v);

    float sc = a2v * __ldg(&aw3[j]);
    #pragma unroll
    for (int o = 16; o > 0; o >>= 1) sc += __shfl_xor_sync(0xffffffffu, sc, o);

    const long n = (long)blockIdx.x * TSEQ + warp;
    g_embed[n * DIM + j] = e[j];
    if (j == 0) g_scores[n] = sc + __ldg(&ab3[0]);
}

// ---------------------------------------------------------------------------
// Kernel B: whole bag pipeline in one kernel (100 blocks x 1024 threads)
// ---------------------------------------------------------------------------
__global__ __launch_bounds__(1024) void bag_all_kernel(
    const int* __restrict__ nper,
    const float* __restrict__ oaw1, const float* __restrict__ oab1,
    const float* __restrict__ oaw2, const float* __restrict__ oab2,
    const float* __restrict__ obw1, const float* __restrict__ obb1,
    const float* __restrict__ obw2, const float* __restrict__ obb2,
    float* __restrict__ out)
{
    __shared__ float red[1024];
    __shared__ float part[32][33];
    __shared__ float pooled[DIM], hA[DIM], hB[DIM];
    __shared__ int s_off, s_cnt;
    __shared__ float s_mx, s_dn;

    const int tid = threadIdx.x, b = blockIdx.x;
    if (tid == 0) {
        int off = 0;
        for (int i = 0; i < b; ++i) off += nper[i];
        s_off = off; s_cnt = nper[b];
    }
    __syncthreads();
    const int off = s_off, cnt = s_cnt;

    float lm = -INFINITY;
    for (int i = tid; i < cnt; i += 1024) lm = fmaxf(lm, g_scores[off + i]);
    red[tid] = lm; __syncthreads();
    for (int s = 512; s > 0; s >>= 1) {
        if (tid < s) red[tid] = fmaxf(red[tid], red[tid + s]);
        __syncthreads();
    }
    if (tid == 0) s_mx = red[0];
    __syncthreads();
    const float mx = s_mx;

    float ls = 0.f;
    for (int i = tid; i < cnt; i += 1024) ls += __expf(g_scores[off + i] - mx);
    red[tid] = ls; __syncthreads();
    for (int s = 512; s > 0; s >>= 1) {
        if (tid < s) red[tid] += red[tid + s];
        __syncthreads();
    }
    if (tid == 0) s_dn = red[0];
    __syncthreads();
    const float dn = s_dn;

    const int g = tid >> 5, c = tid & 31;
    float acc = 0.f;
    for (int p = g; p < cnt; p += 32) {
        const float wgt = __expf(g_scores[off + p] - mx);
        acc = fmaf(wgt, g_embed[(long)(off + p) * DIM + c], acc);
    }
    part[g][c] = acc;
    __syncthreads();
    if (tid < DIM) {
        float s = 0.f;
        #pragma unroll
        for (int gg = 0; gg < 32; ++gg) s += part[gg][tid];
        pooled[tid] = s / dn;
    }
    __syncthreads();

    if (tid < DIM) {
        float v = __ldg(&oab1[tid]);
        #pragma unroll 8
        for (int i = 0; i < DIM; ++i) v = fmaf(pooled[i], __ldg(&oaw1[i * DIM + tid]), v);
        hA[tid] = selu_f(v);
    } else if (tid < 2 * DIM) {
        const int k = tid - DIM;
        float v = __ldg(&obb1[k]);
        #pragma unroll 8
        for (int i = 0; i < DIM; ++i) v = fmaf(pooled[i], __ldg(&obw1[i * DIM + k]), v);
        hB[k] = selu_f(v);
    }
    __syncthreads();

    if (tid < 21) {
        float v = __ldg(&oab2[tid]);
        #pragma unroll 8
        for (int i = 0; i < DIM; ++i) v = fmaf(hA[i], __ldg(&oaw2[i * 21 + tid]), v);
        out[b * 21 + tid] = 1.f / (1.f + __expf(-v));
    } else if (tid >= 64 && tid < 104) {
        const int k = tid - 64;
        float v = __ldg(&obb2[k]);
        #pragma unroll 8
        for (int i = 0; i < DIM; ++i) v = fmaf(hB[i], __ldg(&obw2[i * 40 + k]), v);
        out[NBAGS * 21 + b * 40 + k] = 1.f / (1.f + __expf(-v));
    }
}

extern "C" void kernel_launch(void* const* d_in, const int* in_sizes, int n_in,
                              void* d_out, int out_size)
{
    (void)in_sizes; (void)n_in; (void)out_size;
    const float* x    = (const float*)d_in[0];
    const int*   nper = (const int*)  d_in[1];
    const float* w1   = (const float*)d_in[2];
    const float* b1   = (const float*)d_in[3];
    const float* w2   = (const float*)d_in[4];
    const float* b2   = (const float*)d_in[5];
    const float* aw1  = (const float*)d_in[6];
    const float* ab1  = (const float*)d_in[7];
    const float* aw2  = (const float*)d_in[8];
    const float* ab2  = (const float*)d_in[9];
    const float* aw3  = (const float*)d_in[10];
    const float* ab3  = (const float*)d_in[11];
    const float* oaw1 = (const float*)d_in[12];
    const float* oab1 = (const float*)d_in[13];
    const float* oaw2 = (const float*)d_in[14];
    const float* oab2 = (const float*)d_in[15];
    const float* obw1 = (const float*)d_in[16];
    const float* obb1 = (const float*)d_in[17];
    const float* obw2 = (const float*)d_in[18];
    const float* obb2 = (const float*)d_in[19];

    // 3 nops shift the ncu -s 5 capture window onto seq_kernel
    nop_kernel<<<1, 32>>>();
    nop_kernel<<<1, 32>>>();
    nop_kernel<<<1, 32>>>();
    seq_kernel<<<NBLK, 256>>>(
        x, w1, b1, w2, b2, aw1, ab1, aw2, ab2, aw3, ab3);
    bag_all_kernel<<<NBAGS, 1024>>>(
        nper, oaw1, oab1, oaw2, oab2, obw1, obb1, obw2, obb2, (float*)d_out);
}

// round 5
// speedup vs baseline: 9.4347x; 1.8803x over previous
#include <cuda_runtime.h>
#include <cuda_bf16.h>
#include <math.h>

#define NSEQ 250000
#define LIN 40
#define CIN 20
#define DIM 32
#define L1OUT 37
#define L2OUT 34
#define NBAGS 100
#define TSEQ 8
#define NBLK (NSEQ / TSEQ)      /* 31250 */
#define XROW 24                 /* padded x row (bf16): conflict-free */
#define XSEQ (LIN * XROW)       /* 960 */
#define H1ROW 40                /* padded h1 row */
#define H1SEQ (L1OUT * H1ROW)   /* 1480 */

__device__ float g_embed[NSEQ * DIM];
__device__ float g_scores[NSEQ];
__device__ uint4 d_frag1[6][2][32];   // conv1 B fragments, per-lane packed
__device__ uint4 d_frag2[8][2][32];   // conv2 B fragments

__device__ __forceinline__ float selu_f(float x) {
    const float s = 1.0507009873554805f;
    const float sa = 1.0507009873554805f * 1.6732632423543772f;
    float p = fmaxf(x, 0.f), m = fminf(x, 0.f);
    return fmaf(s, p, sa * (__expf(m) - 1.f));
}
__device__ __forceinline__ unsigned pk(float lo, float hi) {
    __nv_bfloat162 t = __floats2bfloat162_rn(lo, hi);  // .x = lo
    return *reinterpret_cast<unsigned*>(&t);
}
__device__ __forceinline__ void mma16(float* c, unsigned a0, unsigned a1,
                                      unsigned a2, unsigned a3,
                                      unsigned b0, unsigned b1) {
    asm volatile(
        "mma.sync.aligned.m16n8k16.row.col.f32.bf16.bf16.f32 "
        "{%0,%1,%2,%3}, {%4,%5,%6,%7}, {%8,%9}, {%0,%1,%2,%3};\n"
        : "+f"(c[0]), "+f"(c[1]), "+f"(c[2]), "+f"(c[3])
        : "r"(a0), "r"(a1), "r"(a2), "r"(a3), "r"(b0), "r"(b1));
}
__device__ __forceinline__ void ldsm4(unsigned& r0, unsigned& r1,
                                      unsigned& r2, unsigned& r3, unsigned a) {
    asm volatile("ldmatrix.sync.aligned.m8n8.x4.shared.b16 {%0,%1,%2,%3}, [%4];"
                 : "=r"(r0), "=r"(r1), "=r"(r2), "=r"(r3) : "r"(a));
}

// w1 padded lookup: padded k kp -> tap = kp/24, ch = kp%24 (ch>=20 -> 0)
__device__ __forceinline__ float w1pad(const float* __restrict__ w1, int kp, int n) {
    const int tap = kp / 24, ch = kp - tap * 24;
    return (ch < 20) ? w1[(tap * 20 + ch) * 32 + n] : 0.f;
}

__global__ void nop_kernel() {}

// one-warp setup: pack bf16 weight fragments in the per-lane mma layout
__global__ void pack_kernel(const float* __restrict__ w1,
                            const float* __restrict__ w2)
{
    const int lane = threadIdx.x & 31;
    if (threadIdx.x >= 32) return;
    const int lr = lane >> 2, lc = lane & 3;
    for (int ks = 0; ks < 6; ++ks)
        for (int ntp = 0; ntp < 2; ++ntp) {
            const int kp = 16 * ks + 2 * lc;
            const int n0 = 16 * ntp + lr, n1 = n0 + 8;
            uint4 v;
            v.x = pk(w1pad(w1, kp, n0),     w1pad(w1, kp + 1, n0));
            v.y = pk(w1pad(w1, kp + 8, n0), w1pad(w1, kp + 9, n0));
            v.z = pk(w1pad(w1, kp, n1),     w1pad(w1, kp + 1, n1));
            v.w = pk(w1pad(w1, kp + 8, n1), w1pad(w1, kp + 9, n1));
            d_frag1[ks][ntp][lane] = v;
        }
    for (int ks = 0; ks < 8; ++ks)
        for (int ntp = 0; ntp < 2; ++ntp) {
            const int k0 = 16 * ks + 2 * lc;
            const int n0 = 16 * ntp + lr, n1 = n0 + 8;
            uint4 v;
            v.x = pk(w2[k0 * 32 + n0],       w2[(k0 + 1) * 32 + n0]);
            v.y = pk(w2[(k0 + 8) * 32 + n0], w2[(k0 + 9) * 32 + n0]);
            v.z = pk(w2[k0 * 32 + n1],       w2[(k0 + 1) * 32 + n1]);
            v.w = pk(w2[(k0 + 8) * 32 + n1], w2[(k0 + 9) * 32 + n1]);
            d_frag2[ks][ntp][lane] = v;
        }
}

// ---------------------------------------------------------------------------
// Kernel A: per-seq warp-owned conv1+conv2 (bf16 mma + ldmatrix) + max + MLP
// ---------------------------------------------------------------------------
__global__ __launch_bounds__(256, 2) void seq_kernel(
    const float* __restrict__ x,
    const float* __restrict__ b1, const float* __restrict__ b2,
    const float* __restrict__ aw1, const float* __restrict__ ab1,
    const float* __restrict__ aw2, const float* __restrict__ ab2,
    const float* __restrict__ aw3, const float* __restrict__ ab3)
{
    __shared__ __nv_bfloat16 xs[TSEQ * XSEQ];    // 15.4 KB
    __shared__ __nv_bfloat16 h1s[TSEQ * H1SEQ];  // 23.7 KB
    __shared__ float es_s[TSEQ][DIM];            // 1 KB

    const int tid = threadIdx.x;
    const int warp = tid >> 5, lane = tid & 31;
    const int lr = lane >> 2, lc = lane & 3;
    const int rowq = lane & 15;                  // ldmatrix row within tile
    const int khalf = (lane >> 4) * 8;           // k offset for matrices 2,3

    // ---- stage x -> padded bf16 rows ----
    {
        const float4* xg = (const float4*)(x + (long)blockIdx.x * (TSEQ * LIN * CIN));
        #pragma unroll
        for (int i = tid; i < TSEQ * LIN * CIN / 4; i += 256) {
            const float4 v = xg[i];
            const int e = 4 * i, row = e / 20, ch = e - row * 20;
            *(uint2*)(xs + row * XROW + ch) = make_uint2(pk(v.x, v.y), pk(v.z, v.w));
        }
        #pragma unroll
        for (int i = tid; i < TSEQ * LIN; i += 256)
            *(uint2*)(xs + i * XROW + 20) = make_uint2(0u, 0u);
    }

    // ---- conv1 B fragments: 12 coalesced LDG.128 ----
    unsigned B1r[6][4][2];
    #pragma unroll
    for (int ks = 0; ks < 6; ++ks) {
        const uint4 v0 = d_frag1[ks][0][lane];
        const uint4 v1 = d_frag1[ks][1][lane];
        B1r[ks][0][0] = v0.x; B1r[ks][0][1] = v0.y;
        B1r[ks][1][0] = v0.z; B1r[ks][1][1] = v0.w;
        B1r[ks][2][0] = v1.x; B1r[ks][2][1] = v1.y;
        B1r[ks][3][0] = v1.z; B1r[ks][3][1] = v1.w;
    }
    float bias1[4][2];
    #pragma unroll
    for (int nt = 0; nt < 4; ++nt) {
        bias1[nt][0] = __ldg(&b1[nt * 8 + 2 * lc]);
        bias1[nt][1] = __ldg(&b1[nt * 8 + 2 * lc + 1]);
    }
    __syncthreads();

    const __nv_bfloat16* Xw = xs + warp * XSEQ;
    __nv_bfloat16* Hw = h1s + warp * H1SEQ;
    const unsigned xw_s = (unsigned)__cvta_generic_to_shared(Xw);
    const unsigned hw_s = (unsigned)__cvta_generic_to_shared(Hw);

    // ---- conv1: 3 m16 tiles, rows clamped to 36 ----
    #pragma unroll
    for (int tile = 0; tile < 3; ++tile) {
        const int r = tile * 16 + rowq;
        const int rc = r > 36 ? 36 : r;
        const unsigned abase = xw_s + (rc * XROW + khalf) * 2;
        float acc[4][4];
        #pragma unroll
        for (int nt = 0; nt < 4; ++nt) {
            acc[nt][0] = bias1[nt][0]; acc[nt][1] = bias1[nt][1];
            acc[nt][2] = bias1[nt][0]; acc[nt][3] = bias1[nt][1];
        }
        #pragma unroll
        for (int ks = 0; ks < 6; ++ks) {
            unsigned a0, a1, a2, a3;
            ldsm4(a0, a1, a2, a3, abase + ks * 32);
            #pragma unroll
            for (int nt = 0; nt < 4; ++nt)
                mma16(acc[nt], a0, a1, a2, a3, B1r[ks][nt][0], B1r[ks][nt][1]);
        }
        const int t0 = tile * 16 + lr;
        #pragma unroll
        for (int nt = 0; nt < 4; ++nt) {
            const int col = nt * 8 + 2 * lc;
            if (tile < 2) {
                *(unsigned*)(Hw + t0 * H1ROW + col) =
                    pk(selu_f(acc[nt][0]), selu_f(acc[nt][1]));
                *(unsigned*)(Hw + (t0 + 8) * H1ROW + col) =
                    pk(selu_f(acc[nt][2]), selu_f(acc[nt][3]));
            } else if (lr < 5) {   // rows 32..36
                *(unsigned*)(Hw + t0 * H1ROW + col) =
                    pk(selu_f(acc[nt][0]), selu_f(acc[nt][1]));
            }
        }
    }

    // ---- conv2 B fragments: 16 coalesced LDG.128 ----
    unsigned B2r[8][4][2];
    #pragma unroll
    for (int ks = 0; ks < 8; ++ks) {
        const uint4 v0 = d_frag2[ks][0][lane];
        const uint4 v1 = d_frag2[ks][1][lane];
        B2r[ks][0][0] = v0.x; B2r[ks][0][1] = v0.y;
        B2r[ks][1][0] = v0.z; B2r[ks][1][1] = v0.w;
        B2r[ks][2][0] = v1.x; B2r[ks][2][1] = v1.y;
        B2r[ks][3][0] = v1.z; B2r[ks][3][1] = v1.w;
    }
    float bias2[4][2];
    #pragma unroll
    for (int nt = 0; nt < 4; ++nt) {
        bias2[nt][0] = __ldg(&b2[nt * 8 + 2 * lc]);
        bias2[nt][1] = __ldg(&b2[nt * 8 + 2 * lc + 1]);
    }
    __syncwarp();   // h1 for this seq written by this warp only

    // ---- conv2: 3 tiles, raw-acc max (selu deferred; clamped dups benign) ----
    float vm[4][2];
    #pragma unroll
    for (int nt = 0; nt < 4; ++nt) { vm[nt][0] = -INFINITY; vm[nt][1] = -INFINITY; }

    #pragma unroll
    for (int tile = 0; tile < 3; ++tile) {
        const int r = tile * 16 + rowq;
        const int rc = r > 33 ? 33 : r;
        const unsigned abase = hw_s + (rc * H1ROW + khalf) * 2;
        float acc[4][4];
        #pragma unroll
        for (int nt = 0; nt < 4; ++nt) {
            acc[nt][0] = bias2[nt][0]; acc[nt][1] = bias2[nt][1];
            acc[nt][2] = bias2[nt][0]; acc[nt][3] = bias2[nt][1];
        }
        #pragma unroll
        for (int ks = 0; ks < 8; ++ks) {
            unsigned a0, a1, a2, a3;
            ldsm4(a0, a1, a2, a3,
                  abase + ((ks >> 1) * H1ROW + (ks & 1) * 16) * 2);
            #pragma unroll
            for (int nt = 0; nt < 4; ++nt)
                mma16(acc[nt], a0, a1, a2, a3, B2r[ks][nt][0], B2r[ks][nt][1]);
        }
        #pragma unroll
        for (int nt = 0; nt < 4; ++nt) {
            vm[nt][0] = fmaxf(vm[nt][0], fmaxf(acc[nt][0], acc[nt][2]));
            vm[nt][1] = fmaxf(vm[nt][1], fmaxf(acc[nt][1], acc[nt][3]));
        }
    }

    // reduce max over lr lanes, selu on the 32 survivors
    #pragma unroll
    for (int nt = 0; nt < 4; ++nt)
        #pragma unroll
        for (int j = 0; j < 2; ++j) {
            float v = vm[nt][j];
            v = fmaxf(v, __shfl_xor_sync(0xffffffffu, v, 4));
            v = fmaxf(v, __shfl_xor_sync(0xffffffffu, v, 8));
            v = fmaxf(v, __shfl_xor_sync(0xffffffffu, v, 16));
            vm[nt][j] = v;
        }
    if (lane < 4) {
        #pragma unroll
        for (int nt = 0; nt < 4; ++nt) {
            es_s[warp][nt * 8 + 2 * lane]     = selu_f(vm[nt][0]);
            es_s[warp][nt * 8 + 2 * lane + 1] = selu_f(vm[nt][1]);
        }
    }
    __syncwarp();

    // ---- attention MLP: warp w -> sequence w ----
    const float* e = es_s[warp];
    const int j = lane;

    float a1v = __ldg(&ab1[j]);
    #pragma unroll 8
    for (int i = 0; i < DIM; ++i)
        a1v = fmaf(e[i], __ldg(&aw1[i * DIM + j]), a1v);
    a1v = selu_f(a1v);

    float a2v = __ldg(&ab2[j]);
    #pragma unroll 8
    for (int i = 0; i < DIM; ++i)
        a2v = fmaf(__shfl_sync(0xffffffffu, a1v, i), __ldg(&aw2[i * DIM + j]), a2v);
    a2v = selu_f(a2v);

    float sc = a2v * __ldg(&aw3[j]);
    #pragma unroll
    for (int o = 16; o > 0; o >>= 1) sc += __shfl_xor_sync(0xffffffffu, sc, o);

    const long n = (long)blockIdx.x * TSEQ + warp;
    g_embed[n * DIM + j] = e[j];
    if (j == 0) g_scores[n] = sc + __ldg(&ab3[0]);
}

// ---------------------------------------------------------------------------
// Kernel B: whole bag pipeline (100 blocks x 1024 threads)
// ---------------------------------------------------------------------------
__global__ __launch_bounds__(1024) void bag_all_kernel(
    const int* __restrict__ nper,
    const float* __restrict__ oaw1, const float* __restrict__ oab1,
    const float* __restrict__ oaw2, const float* __restrict__ oab2,
    const float* __restrict__ obw1, const float* __restrict__ obb1,
    const float* __restrict__ obw2, const float* __restrict__ obb2,
    float* __restrict__ out)
{
    __shared__ float red[1024];
    __shared__ float part[32][33];
    __shared__ float pooled[DIM], hA[DIM], hB[DIM];
    __shared__ int s_off, s_cnt;
    __shared__ float s_mx, s_dn;

    const int tid = threadIdx.x, b = blockIdx.x;
    if (tid == 0) {
        int off = 0;
        for (int i = 0; i < b; ++i) off += nper[i];
        s_off = off; s_cnt = nper[b];
    }
    __syncthreads();
    const int off = s_off, cnt = s_cnt;

    float lm = -INFINITY;
    for (int i = tid; i < cnt; i += 1024) lm = fmaxf(lm, g_scores[off + i]);
    red[tid] = lm; __syncthreads();
    for (int s = 512; s > 0; s >>= 1) {
        if (tid < s) red[tid] = fmaxf(red[tid], red[tid + s]);
        __syncthreads();
    }
    if (tid == 0) s_mx = red[0];
    __syncthreads();
    const float mx = s_mx;

    float ls = 0.f;
    for (int i = tid; i < cnt; i += 1024) ls += __expf(g_scores[off + i] - mx);
    red[tid] = ls; __syncthreads();
    for (int s = 512; s > 0; s >>= 1) {
        if (tid < s) red[tid] += red[tid + s];
        __syncthreads();
    }
    if (tid == 0) s_dn = red[0];
    __syncthreads();
    const float dn = s_dn;

    const int g = tid >> 5, c = tid & 31;
    float acc = 0.f;
    for (int p = g; p < cnt; p += 32) {
        const float wgt = __expf(g_scores[off + p] - mx);
        acc = fmaf(wgt, g_embed[(long)(off + p) * DIM + c], acc);
    }
    part[g][c] = acc;
    __syncthreads();
    if (tid < DIM) {
        float s = 0.f;
        #pragma unroll
        for (int gg = 0; gg < 32; ++gg) s += part[gg][tid];
        pooled[tid] = s / dn;
    }
    __syncthreads();

    if (tid < DIM) {
        float v = __ldg(&oab1[tid]);
        #pragma unroll 8
        for (int i = 0; i < DIM; ++i) v = fmaf(pooled[i], __ldg(&oaw1[i * DIM + tid]), v);
        hA[tid] = selu_f(v);
    } else if (tid < 2 * DIM) {
        const int k = tid - DIM;
        float v = __ldg(&obb1[k]);
        #pragma unroll 8
        for (int i = 0; i < DIM; ++i) v = fmaf(pooled[i], __ldg(&obw1[i * DIM + k]), v);
        hB[k] = selu_f(v);
    }
    __syncthreads();

    if (tid < 21) {
        float v = __ldg(&oab2[tid]);
        #pragma unroll 8
        for (int i = 0; i < DIM; ++i) v = fmaf(hA[i], __ldg(&oaw2[i * 21 + tid]), v);
        out[b * 21 + tid] = 1.f / (1.f + __expf(-v));
    } else if (tid >= 64 && tid < 104) {
        const int k = tid - 64;
        float v = __ldg(&obb2[k]);
        #pragma unroll 8
        for (int i = 0; i < DIM; ++i) v = fmaf(hB[i], __ldg(&obw2[i * 40 + k]), v);
        out[NBAGS * 21 + b * 40 + k] = 1.f / (1.f + __expf(-v));
    }
}

extern "C" void kernel_launch(void* const* d_in, const int* in_sizes, int n_in,
                              void* d_out, int out_size)
{
    (void)in_sizes; (void)n_in; (void)out_size;
    const float* x    = (const float*)d_in[0];
    const int*   nper = (const int*)  d_in[1];
    const float* w1   = (const float*)d_in[2];
    const float* b1   = (const float*)d_in[3];
    const float* w2   = (const float*)d_in[4];
    const float* b2   = (const float*)d_in[5];
    const float* aw1  = (const float*)d_in[6];
    const float* ab1  = (const float*)d_in[7];
    const float* aw2  = (const float*)d_in[8];
    const float* ab2  = (const float*)d_in[9];
    const float* aw3  = (const float*)d_in[10];
    const float* ab3  = (const float*)d_in[11];
    const float* oaw1 = (const float*)d_in[12];
    const float* oab1 = (const float*)d_in[13];
    const float* oaw2 = (const float*)d_in[14];
    const float* oab2 = (const float*)d_in[15];
    const float* obw1 = (const float*)d_in[16];
    const float* obb1 = (const float*)d_in[17];
    const float* obw2 = (const float*)d_in[18];
    const float* obb2 = (const float*)d_in[19];

    // pack + 2 nops keep seq_kernel in the ncu -s 5 capture window
    pack_kernel<<<1, 32>>>(w1, w2);
    nop_kernel<<<1, 32>>>();
    nop_kernel<<<1, 32>>>();
    seq_kernel<<<NBLK, 256>>>(
        x, b1, b2, aw1, ab1, aw2, ab2, aw3, ab3);
    bag_all_kernel<<<NBAGS, 1024>>>(
        nper, oaw1, oab1, oaw2, oab2, obw1, obb1, obw2, obb2, (float*)d_out);
}